// round 2
// baseline (speedup 1.0000x reference)
#include <cuda_runtime.h>
#include <mma.h>

using namespace nvcuda;

// ---------------------------------------------------------------------------
// Fused ExtractorMLP:
//   f12 = concat(emb[col], emb[row])            [E, 256]
//   x1  = relu(f12 @ W1 + b1)                   [E, 512]
//   x2  = relu(x1 @ W2 + b2)                    [E, 128]
//   out = x2 @ W3 + b3                          [E, 1]
// One CTA = 128 edges. tf32 wmma (m16n16k8), fp32 accumulate.
// edge_index is INT32 (JAX x64 disabled => int64 request silently -> int32).
// ---------------------------------------------------------------------------

#define LDF 264               // f12 smem leading dim (256 + 8 pad)
#define LDX 136               // x1-chunk smem leading dim (128 + 8 pad)
#define M_TILE 128            // edges per CTA
#define THREADS 256

__global__ void __launch_bounds__(THREADS, 1)
extractor_mlp_kernel(const float* __restrict__ emb,
                     const int* __restrict__ edge_index,
                     const float* __restrict__ W1, const float* __restrict__ b1,
                     const float* __restrict__ W2, const float* __restrict__ b2,
                     const float* __restrict__ W3, const float* __restrict__ b3,
                     float* __restrict__ out, int E)
{
    extern __shared__ float smem[];
    float* f12 = smem;                      // [128][LDF]
    float* x1c = smem + M_TILE * LDF;       // [128][LDX]  (also reused for x2)
    __shared__ int s_col[M_TILE];
    __shared__ int s_row[M_TILE];

    const int tid  = threadIdx.x;
    const int base = blockIdx.x * M_TILE;

    // ---- load edge endpoint indices (int32!) -----------------------------
    if (tid < M_TILE) {
        int e = base + tid;
        s_col[tid] = (e < E) ? edge_index[e] : -1;
    } else {
        int e = base + (tid - M_TILE);
        s_row[tid - M_TILE] = (e < E) ? edge_index[E + e] : -1;
    }
    __syncthreads();

    // ---- gather f12 = [emb[col] | emb[row]] into smem (float4) ----------
    for (int i = tid; i < M_TILE * 64; i += THREADS) {
        int m = i >> 6;          // edge within tile
        int q = i & 63;          // float4 index within 256-float row
        int idx = (q < 32) ? s_col[m] : s_row[m];
        int qq  = (q < 32) ? q : (q - 32);
        float4 v;
        if (idx >= 0)
            v = ((const float4*)(emb + (long long)idx * 128))[qq];
        else
            v = make_float4(0.f, 0.f, 0.f, 0.f);
        *(float4*)(f12 + m * LDF + q * 4) = v;
    }
    __syncthreads();

    // ---- warp tiling: 2 (M) x 4 (N); each warp computes 64x32 -----------
    const int w  = tid >> 5;
    const int wm = (w & 1) * 64;   // M offset within 128
    const int wn = (w >> 1) * 32;  // N offset within 128

    wmma::fragment<wmma::accumulator, 16, 16, 8, float> acc2[4][2];
    #pragma unroll
    for (int i = 0; i < 4; ++i)
        #pragma unroll
        for (int j = 0; j < 2; ++j)
            wmma::fill_fragment(acc2[i][j], 0.0f);

    #pragma unroll 1
    for (int c = 0; c < 4; ++c) {
        // ----- layer 1 chunk: x1c = f12 @ W1[:, c*128 : c*128+128] -------
        wmma::fragment<wmma::accumulator, 16, 16, 8, float> acc1[4][2];
        #pragma unroll
        for (int i = 0; i < 4; ++i)
            #pragma unroll
            for (int j = 0; j < 2; ++j)
                wmma::fill_fragment(acc1[i][j], 0.0f);

        #pragma unroll 4
        for (int k = 0; k < 256; k += 8) {
            wmma::fragment<wmma::matrix_a, 16, 16, 8, wmma::precision::tf32, wmma::row_major> a[4];
            #pragma unroll
            for (int i = 0; i < 4; ++i) {
                wmma::load_matrix_sync(a[i], f12 + (wm + i * 16) * LDF + k, LDF);
                #pragma unroll
                for (int t = 0; t < a[i].num_elements; ++t)
                    a[i].x[t] = wmma::__float_to_tf32(a[i].x[t]);
            }
            wmma::fragment<wmma::matrix_b, 16, 16, 8, wmma::precision::tf32, wmma::row_major> bf[2];
            #pragma unroll
            for (int j = 0; j < 2; ++j) {
                wmma::load_matrix_sync(bf[j], W1 + (long long)k * 512 + c * 128 + wn + j * 16, 512);
                #pragma unroll
                for (int t = 0; t < bf[j].num_elements; ++t)
                    bf[j].x[t] = wmma::__float_to_tf32(bf[j].x[t]);
            }
            #pragma unroll
            for (int i = 0; i < 4; ++i)
                #pragma unroll
                for (int j = 0; j < 2; ++j)
                    wmma::mma_sync(acc1[i][j], a[i], bf[j], acc1[i][j]);
        }

        // protect x1c: previous chunk's layer-2 reads must be done
        __syncthreads();

        #pragma unroll
        for (int i = 0; i < 4; ++i)
            #pragma unroll
            for (int j = 0; j < 2; ++j)
                wmma::store_matrix_sync(x1c + (wm + i * 16) * LDX + wn + j * 16,
                                        acc1[i][j], LDX, wmma::mem_row_major);
        __syncthreads();

        // ----- bias + relu in smem ---------------------------------------
        for (int i = tid; i < 128 * 128; i += THREADS) {
            int m = i >> 7, n = i & 127;
            float v = x1c[m * LDX + n] + b1[c * 128 + n];
            x1c[m * LDX + n] = fmaxf(v, 0.0f);
        }
        __syncthreads();

        // ----- layer 2 partial: acc2 += x1c @ W2[c*128 : c*128+128, :] ---
        #pragma unroll 4
        for (int k = 0; k < 128; k += 8) {
            wmma::fragment<wmma::matrix_a, 16, 16, 8, wmma::precision::tf32, wmma::row_major> a[4];
            #pragma unroll
            for (int i = 0; i < 4; ++i) {
                wmma::load_matrix_sync(a[i], x1c + (wm + i * 16) * LDX + k, LDX);
                #pragma unroll
                for (int t = 0; t < a[i].num_elements; ++t)
                    a[i].x[t] = wmma::__float_to_tf32(a[i].x[t]);
            }
            wmma::fragment<wmma::matrix_b, 16, 16, 8, wmma::precision::tf32, wmma::row_major> bf[2];
            #pragma unroll
            for (int j = 0; j < 2; ++j) {
                wmma::load_matrix_sync(bf[j], W2 + (long long)(c * 128 + k) * 128 + wn + j * 16, 128);
                #pragma unroll
                for (int t = 0; t < bf[j].num_elements; ++t)
                    bf[j].x[t] = wmma::__float_to_tf32(bf[j].x[t]);
            }
            #pragma unroll
            for (int i = 0; i < 4; ++i)
                #pragma unroll
                for (int j = 0; j < 2; ++j)
                    wmma::mma_sync(acc2[i][j], a[i], bf[j], acc2[i][j]);
        }
    }

    // ---- store x2 (pre-bias) into smem (reuse x1c region) ---------------
    __syncthreads();
    #pragma unroll
    for (int i = 0; i < 4; ++i)
        #pragma unroll
        for (int j = 0; j < 2; ++j)
            wmma::store_matrix_sync(x1c + (wm + i * 16) * LDX + wn + j * 16,
                                    acc2[i][j], LDX, wmma::mem_row_major);
    __syncthreads();

    // ---- layer 3: out[m] = relu(x2[m]+b2) . W3 + b3 (2 threads / edge) --
    {
        int m = tid >> 1;
        int h = tid & 1;
        const float* xr = x1c + m * LDX + h * 64;
        float s = 0.0f;
        #pragma unroll 8
        for (int n = 0; n < 64; ++n) {
            float v = fmaxf(xr[n] + b2[h * 64 + n], 0.0f);
            s += v * W3[h * 64 + n];
        }
        s += __shfl_xor_sync(0xffffffffu, s, 1);
        int e = base + m;
        if (h == 0 && e < E)
            out[e] = s + b3[0];
    }
}

extern "C" void kernel_launch(void* const* d_in, const int* in_sizes, int n_in,
                              void* d_out, int out_size)
{
    const float* emb = (const float*)d_in[0];
    const int*   ei  = (const int*)d_in[1];     // int32! (JAX x64 disabled)
    const float* W1  = (const float*)d_in[2];
    const float* b1  = (const float*)d_in[3];
    const float* W2  = (const float*)d_in[4];
    const float* b2  = (const float*)d_in[5];
    const float* W3  = (const float*)d_in[6];
    const float* b3  = (const float*)d_in[7];
    float* out = (float*)d_out;

    const int E = out_size;   // output is [E, 1] float32

    size_t smem_bytes = (size_t)(M_TILE * LDF + M_TILE * LDX) * sizeof(float);
    cudaFuncSetAttribute(extractor_mlp_kernel,
                         cudaFuncAttributeMaxDynamicSharedMemorySize,
                         (int)smem_bytes);

    int grid = (E + M_TILE - 1) / M_TILE;
    extractor_mlp_kernel<<<grid, THREADS, smem_bytes>>>(
        emb, ei, W1, b1, W2, b2, W3, b3, out, E);
}